// round 3
// baseline (speedup 1.0000x reference)
#include <cuda_runtime.h>
#include <cuda_bf16.h>
#include <math.h>

// ---------------- problem constants ----------------
#define S_LEN   8192
#define L_CHARS 16
#define CHAR_DIM 64
#define WORD_DIM 256
#define CHAR_HID 128
#define WORD_HID 512
#define N_TAG   64
#define CK      192              // CHAR_DIM + CHAR_HID (char gemm K)
#define WK      384              // WORD_DIM + CHAR_HID (word input gemm K)
#define GW      128              // persistent CTAs for word LSTM

// ---------------- device scratch (no cudaMalloc allowed) ----------------
__device__ float g_A[S_LEN * CK];          // char LSTM gemm input [ce_t | h]
__device__ float g_gates[S_LEN * 512];     // char gates
__device__ float g_c[S_LEN * CHAR_HID];    // char cell state
__device__ float g_cf[S_LEN * CHAR_HID];   // char features
__device__ float g_Wc[512 * CK];           // concat [c_Wih | c_Whh]
__device__ float g_bc[512];                // c_bih + c_bhh
__device__ float g_bw[2048];               // w_bih + w_bhh
__device__ float g_F[S_LEN * WK];          // word feats [we | cf]
__device__ float g_wg[S_LEN * 2048];       // word input gates (CTA-blocked)
__device__ float g_h[(S_LEN + 1) * 512];   // word hidden history (row0 = 0)
__device__ unsigned long long g_bar_cnt;   // grid barrier (self-resetting)
__device__ unsigned int g_bar_gen;         // monotonic, compared relatively

__device__ __forceinline__ float sigmoidf_(float x) { return 1.f / (1.f + expf(-x)); }

// ---------------- prep: concat weights, biases, init buffers ----------------
__global__ void prep_kernel(const int* __restrict__ chars,
                            const float* __restrict__ char_embed,
                            const float* __restrict__ c_Wih,
                            const float* __restrict__ c_Whh,
                            const float* __restrict__ c_bih,
                            const float* __restrict__ c_bhh,
                            const float* __restrict__ w_bih,
                            const float* __restrict__ w_bhh) {
    int tid = blockIdx.x * blockDim.x + threadIdx.x;
    int stride = gridDim.x * blockDim.x;
    for (int i = tid; i < 512 * CK; i += stride) {
        int j = i / CK, k = i - j * CK;
        g_Wc[i] = (k < CHAR_DIM) ? c_Wih[j * CHAR_DIM + k]
                                 : c_Whh[j * CHAR_HID + (k - CHAR_DIM)];
    }
    for (int i = tid; i < 512; i += stride) g_bc[i] = c_bih[i] + c_bhh[i];
    for (int i = tid; i < 2048; i += stride) g_bw[i] = w_bih[i] + w_bhh[i];
    for (int i = tid; i < S_LEN * CHAR_HID; i += stride) g_c[i] = 0.f;
    for (int i = tid; i < 512; i += stride) g_h[i] = 0.f;
    // char gemm input for t=0: ce in cols [0,64), zeros (h0) in [64,192)
    for (int i = tid; i < S_LEN * CK; i += stride) {
        int b = i / CK, k = i - b * CK;
        g_A[i] = (k < CHAR_DIM)
                   ? char_embed[chars[b * L_CHARS + 0] * CHAR_DIM + k]
                   : 0.f;
    }
}

// ---------------- generic fp32 GEMM: C = A(MxK) * B(NxK)^T + bias ----------------
// BM=128 BN=64 BK=16, 256 threads, 8x4 per-thread tile.
// mode 0: C[row*ldc+col] = acc + bias[col]
// mode 1: word-gate blocked store for the recurrent kernel's layout
__global__ void __launch_bounds__(256) gemm_bias(const float* __restrict__ A,
                                                 const float* __restrict__ B,
                                                 const float* __restrict__ bias,
                                                 float* __restrict__ C,
                                                 int K, int ldc, int mode) {
    __shared__ float sA[2][16][129];
    __shared__ float sB[2][16][65];
    const int bm = blockIdx.x << 7;
    const int bn = blockIdx.y << 6;
    const int tid = threadIdx.x;
    const int tx = tid & 15;
    const int ty = tid >> 4;
    const int lrow = tid >> 2;           // loader row (A: lrow & lrow+64, B: lrow)
    const int kq = (tid & 3) << 2;       // loader k-quad base

    const float* Aptr = A + (size_t)(bm + lrow) * K + kq;
    const float* Bptr = B + (size_t)(bn + lrow) * K + kq;

    float acc[8][4];
#pragma unroll
    for (int i = 0; i < 8; i++)
#pragma unroll
        for (int j = 0; j < 4; j++) acc[i][j] = 0.f;

    // prologue: fill buffer 0
    {
        float4 v0 = *(const float4*)(Aptr);
        float4 v1 = *(const float4*)(Aptr + (size_t)64 * K);
        float4 vb = *(const float4*)(Bptr);
        sA[0][kq + 0][lrow] = v0.x; sA[0][kq + 1][lrow] = v0.y;
        sA[0][kq + 2][lrow] = v0.z; sA[0][kq + 3][lrow] = v0.w;
        sA[0][kq + 0][lrow + 64] = v1.x; sA[0][kq + 1][lrow + 64] = v1.y;
        sA[0][kq + 2][lrow + 64] = v1.z; sA[0][kq + 3][lrow + 64] = v1.w;
        sB[0][kq + 0][lrow] = vb.x; sB[0][kq + 1][lrow] = vb.y;
        sB[0][kq + 2][lrow] = vb.z; sB[0][kq + 3][lrow] = vb.w;
    }
    __syncthreads();

    const int nk = K >> 4;
    for (int kt = 0; kt < nk; kt++) {
        const int cur = kt & 1;
        float4 v0, v1, vb;
        const bool pf = (kt + 1) < nk;
        if (pf) {
            const float* Ap = Aptr + ((kt + 1) << 4);
            v0 = *(const float4*)(Ap);
            v1 = *(const float4*)(Ap + (size_t)64 * K);
            vb = *(const float4*)(Bptr + ((kt + 1) << 4));
        }
#pragma unroll
        for (int kk = 0; kk < 16; kk++) {
            float a[8], b[4];
#pragma unroll
            for (int i = 0; i < 8; i++) a[i] = sA[cur][kk][ty + 16 * i];
#pragma unroll
            for (int j = 0; j < 4; j++) b[j] = sB[cur][kk][tx + 16 * j];
#pragma unroll
            for (int i = 0; i < 8; i++)
#pragma unroll
                for (int j = 0; j < 4; j++)
                    acc[i][j] = fmaf(a[i], b[j], acc[i][j]);
        }
        if (pf) {
            const int nb = cur ^ 1;
            sA[nb][kq + 0][lrow] = v0.x; sA[nb][kq + 1][lrow] = v0.y;
            sA[nb][kq + 2][lrow] = v0.z; sA[nb][kq + 3][lrow] = v0.w;
            sA[nb][kq + 0][lrow + 64] = v1.x; sA[nb][kq + 1][lrow + 64] = v1.y;
            sA[nb][kq + 2][lrow + 64] = v1.z; sA[nb][kq + 3][lrow + 64] = v1.w;
            sB[nb][kq + 0][lrow] = vb.x; sB[nb][kq + 1][lrow] = vb.y;
            sB[nb][kq + 2][lrow] = vb.z; sB[nb][kq + 3][lrow] = vb.w;
        }
        __syncthreads();
    }

    if (mode == 0) {
#pragma unroll
        for (int i = 0; i < 8; i++) {
            int row = bm + ty + 16 * i;
#pragma unroll
            for (int j = 0; j < 4; j++) {
                int col = bn + tx + 16 * j;
                C[(size_t)row * ldc + col] = acc[i][j] + bias[col];
            }
        }
    } else {
        // blocked store: gate row j -> (cta = (j&511)>>2, r = (j&511&3)*4 + (j>>9))
#pragma unroll
        for (int i = 0; i < 8; i++) {
            int row = bm + ty + 16 * i;
#pragma unroll
            for (int j = 0; j < 4; j++) {
                int col = bn + tx + 16 * j;
                int gt = col >> 9;
                int hh = col & 511;
                int dst = (hh >> 2) * 16 + (hh & 3) * 4 + gt;
                C[(size_t)row * 2048 + dst] = acc[i][j] + bias[col];
            }
        }
    }
}

// ---------------- char LSTM pointwise update ----------------
__global__ void char_pointwise(const int* __restrict__ chars,
                               const int* __restrict__ char_lens,
                               const float* __restrict__ char_embed, int t) {
    int idx = blockIdx.x * blockDim.x + threadIdx.x;
    if (idx < S_LEN * CHAR_HID) {
        int b = idx >> 7, j = idx & 127;
        const float* gr = g_gates + b * 512;
        float i_ = sigmoidf_(gr[j]);
        float f_ = sigmoidf_(gr[128 + j]);
        float gg = tanhf(gr[256 + j]);
        float o_ = sigmoidf_(gr[384 + j]);
        float c = f_ * g_c[idx] + i_ * gg;
        g_c[idx] = c;
        float h = o_ * tanhf(c);
        g_A[b * CK + CHAR_DIM + j] = h;               // input for next step
        if (char_lens[b] - 1 == t) g_cf[idx] = h;     // final char feature
    }
    if (t + 1 < L_CHARS && idx < S_LEN * CHAR_DIM) {
        int b = idx >> 6, k = idx & 63;
        g_A[b * CK + k] = char_embed[chars[b * L_CHARS + (t + 1)] * CHAR_DIM + k];
    }
}

// ---------------- word feature gather ----------------
__global__ void feats_kernel(const int* __restrict__ x,
                             const float* __restrict__ word_embed) {
    int i = blockIdx.x * blockDim.x + threadIdx.x;
    if (i < S_LEN * WK) {
        int s = i / WK, k = i - s * WK;
        g_F[i] = (k < WORD_DIM) ? word_embed[x[s] * WORD_DIM + k]
                                : g_cf[s * CHAR_HID + (k - WORD_DIM)];
    }
}

// ---------------- persistent word LSTM recurrence ----------------
// 128 CTAs x 256 threads. CTA owns 4 hidden units (16 gate rows).
// Thread (r = tid>>4, cg = tid&15): gate row r, h-columns [cg*32, cg*32+32),
// weights register-resident. Reduce over 16 lanes via shfl_xor.
__global__ void __launch_bounds__(256) word_lstm_kernel(const float* __restrict__ Whh) {
    const int cta = blockIdx.x;
    const int tid = threadIdx.x;
    const int r = tid >> 4;
    const int cg = tid & 15;
    const int gt = r & 3;                 // 0:i 1:f 2:g 3:o
    const int hl = r >> 2;
    const int grow = gt * 512 + cta * 4 + hl;

    float4 w[8];
    {
        const float4* wp = (const float4*)(Whh + (size_t)grow * 512 + cg * 32);
#pragma unroll
        for (int i = 0; i < 8; i++) w[i] = wp[i];
    }
    const bool leader = (cg == 0);
    float wg_cur = 0.f, wg_nxt = 0.f;
    if (leader) {
        wg_cur = g_wg[0 * 2048 + cta * 16 + r];
        wg_nxt = g_wg[1 * 2048 + cta * 16 + r];
    }
    float c = 0.f;
    __shared__ float gact[16];

    for (int s = 0; s < S_LEN; s++) {
        // prefetch input gates two steps ahead (DRAM streaming)
        float wg_pf = 0.f;
        if (leader && s + 2 < S_LEN)
            wg_pf = __ldcg(&g_wg[(size_t)(s + 2) * 2048 + cta * 16 + r]);

        const float4* hp = (const float4*)(g_h + (size_t)s * 512 + cg * 32);
        float a0 = 0.f, a1 = 0.f, a2 = 0.f, a3 = 0.f;
#pragma unroll
        for (int i = 0; i < 8; i++) {
            float4 h4 = hp[i];
            a0 = fmaf(w[i].x, h4.x, a0);
            a1 = fmaf(w[i].y, h4.y, a1);
            a2 = fmaf(w[i].z, h4.z, a2);
            a3 = fmaf(w[i].w, h4.w, a3);
        }
        float dot = (a0 + a1) + (a2 + a3);
#pragma unroll
        for (int off = 8; off > 0; off >>= 1)
            dot += __shfl_xor_sync(0xffffffffu, dot, off);

        if (leader) {
            float v = dot + wg_cur;
            gact[r] = (gt == 2) ? tanhf(v) : sigmoidf_(v);
        }
        __syncthreads();
        if (tid < 4) {
            float i_ = gact[tid * 4 + 0];
            float f_ = gact[tid * 4 + 1];
            float g_ = gact[tid * 4 + 2];
            float o_ = gact[tid * 4 + 3];
            c = f_ * c + i_ * g_;
            float h = o_ * tanhf(c);
            g_h[(size_t)(s + 1) * 512 + cta * 4 + tid] = h;
            __threadfence();
        }
        if (leader) { wg_cur = wg_nxt; wg_nxt = wg_pf; }
        __syncthreads();

        // grid barrier: self-resetting counter + relative generation compare
        if (tid == 0) {
            unsigned g0 = *((volatile unsigned*)&g_bar_gen);
            unsigned long long old = atomicAdd(&g_bar_cnt, 1ULL);
            if (old == (unsigned long long)(GW - 1)) {
                atomicExch(&g_bar_cnt, 0ULL);
                __threadfence();
                *((volatile unsigned*)&g_bar_gen) = g0 + 1;
            } else {
                while (*((volatile unsigned*)&g_bar_gen) == g0) { }
            }
            __threadfence();
        }
        __syncthreads();
    }
}

// ---------------- host launch ----------------
extern "C" void kernel_launch(void* const* d_in, const int* in_sizes, int n_in,
                              void* d_out, int out_size) {
    (void)in_sizes; (void)n_in; (void)out_size;
    const int*   x          = (const int*)d_in[0];
    const int*   chars      = (const int*)d_in[1];
    const int*   char_lens  = (const int*)d_in[2];
    const float* word_embed = (const float*)d_in[3];
    const float* char_embed = (const float*)d_in[4];
    const float* c_Wih      = (const float*)d_in[5];
    const float* c_Whh      = (const float*)d_in[6];
    const float* c_bih      = (const float*)d_in[7];
    const float* c_bhh      = (const float*)d_in[8];
    const float* w_Wih      = (const float*)d_in[9];
    const float* w_Whh      = (const float*)d_in[10];
    const float* w_bih      = (const float*)d_in[11];
    const float* w_bhh      = (const float*)d_in[12];
    const float* cls_W      = (const float*)d_in[13];
    const float* cls_b      = (const float*)d_in[14];
    float* out = (float*)d_out;

    float *pA, *pWc, *pbc, *pgates, *pbw, *pF, *pwg, *ph;
    cudaGetSymbolAddress((void**)&pA,     g_A);
    cudaGetSymbolAddress((void**)&pWc,    g_Wc);
    cudaGetSymbolAddress((void**)&pbc,    g_bc);
    cudaGetSymbolAddress((void**)&pgates, g_gates);
    cudaGetSymbolAddress((void**)&pbw,    g_bw);
    cudaGetSymbolAddress((void**)&pF,     g_F);
    cudaGetSymbolAddress((void**)&pwg,    g_wg);
    cudaGetSymbolAddress((void**)&ph,     g_h);

    prep_kernel<<<1024, 256>>>(chars, char_embed, c_Wih, c_Whh,
                               c_bih, c_bhh, w_bih, w_bhh);

    // char LSTM: 16 x (gates GEMM + pointwise)
    for (int t = 0; t < L_CHARS; t++) {
        gemm_bias<<<dim3(S_LEN / 128, 512 / 64), 256>>>(
            pA, pWc, pbc, pgates, CK, 512, 0);
        char_pointwise<<<(S_LEN * CHAR_HID) / 256, 256>>>(
            chars, char_lens, char_embed, t);
    }

    // word features + input-gate precompute (blocked layout, biases folded)
    feats_kernel<<<(S_LEN * WK + 255) / 256, 256>>>(x, word_embed);
    gemm_bias<<<dim3(S_LEN / 128, 2048 / 64), 256>>>(
        pF, w_Wih, pbw, pwg, WK, 2048, 1);

    // sequential word LSTM (persistent cooperative kernel)
    word_lstm_kernel<<<GW, 256>>>(w_Whh);

    // classifier: out = h_all @ cls_W^T + cls_b  (A offset by one row: h[1..S])
    gemm_bias<<<dim3(S_LEN / 128, 1), 256>>>(
        ph + 512, cls_W, cls_b, out, 512, N_TAG, 0);
}